// round 1
// baseline (speedup 1.0000x reference)
#include <cuda_runtime.h>
#include <cstdint>

#define N_NODES 50000
#define A_DIM   65
#define DEG     32
#define HID     16
#define BOT     32

// Composed first layer: Wc = W_se @ W1  (2x16), bc = b_se @ W1 + b1 (16)
__device__ float g_Wc0[HID];
__device__ float g_Wc1[HID];
__device__ float g_bc[HID];

__global__ void setup_weights_kernel(const float* __restrict__ W_se,
                                     const float* __restrict__ b_se,
                                     const float* __restrict__ W1,
                                     const float* __restrict__ b1) {
    int j = threadIdx.x;
    if (j < HID) {
        float wc0 = 0.f, wc1 = 0.f, bc = b1[j];
        #pragma unroll
        for (int e = 0; e < 32; e++) {
            float w1ej = W1[e * HID + j];
            wc0 = fmaf(W_se[e], w1ej, wc0);           // W_se[0][e]
            wc1 = fmaf(W_se[32 + e], w1ej, wc1);      // W_se[1][e]
            bc  = fmaf(b_se[e], w1ej, bc);
        }
        g_Wc0[j] = wc0;
        g_Wc1[j] = wc1;
        g_bc[j]  = bc;
    }
}

__device__ __forceinline__ void fma2(unsigned long long& acc,
                                     unsigned long long a,
                                     unsigned long long b) {
    asm("fma.rn.f32x2 %0, %1, %2, %0;" : "+l"(acc) : "l"(a), "l"(b));
}

__device__ __forceinline__ unsigned long long pack2(float v) {
    unsigned long long r;
    asm("mov.b64 %0, {%1, %1};" : "=l"(r) : "r"(__float_as_uint(v)));
    return r;
}

#define WARPS_PER_BLOCK 4

__global__ __launch_bounds__(WARPS_PER_BLOCK * 32)
void pooling_net_kernel(const float2* __restrict__ corr,       // [N, 65] float2
                        const int*    __restrict__ nei,        // [N*32, 3]
                        const float*  __restrict__ W2,         // [16, 32]
                        const float*  __restrict__ b2,         // [32]
                        float*        __restrict__ out) {      // [N, 32]
    __shared__ float sWc0[HID], sWc1[HID], sbc[HID];
    __shared__ __align__(16) unsigned long long sW2[HID * 16]; // [j][c_pair]
    __shared__ unsigned long long sb2[16];
    __shared__ float red[WARPS_PER_BLOCK][DEG * 33];           // stride-33 pad

    // Stage weights to shared
    if (threadIdx.x < HID) {
        int t = threadIdx.x;
        sWc0[t] = g_Wc0[t];
        sWc1[t] = g_Wc1[t];
        sbc[t]  = g_bc[t];
        sb2[t]  = ((const unsigned long long*)b2)[t];
    }
    for (int i = threadIdx.x; i < HID * 16; i += blockDim.x)
        sW2[i] = ((const unsigned long long*)W2)[i];
    __syncthreads();

    int warp   = (blockIdx.x * blockDim.x + threadIdx.x) >> 5;  // node id
    int lane   = threadIdx.x & 31;                               // neighbor id
    int wlocal = threadIdx.x >> 5;
    if (warp >= N_NODES) return;

    // Gather this neighbor's relative coordinate
    int a = nei[(warp * DEG + lane) * 3 + 1];
    float2 xy = corr[warp * A_DIM + a];

    // Layer 1 (composed 2->16) + relu
    float h1[HID];
    #pragma unroll
    for (int j = 0; j < HID; j++)
        h1[j] = fmaxf(fmaf(xy.x, sWc0[j], fmaf(xy.y, sWc1[j], sbc[j])), 0.f);

    // Layer 2 (16->32) as 16 packed f32x2 accumulators
    unsigned long long acc[16];
    #pragma unroll
    for (int c = 0; c < 16; c++) acc[c] = sb2[c];

    #pragma unroll
    for (int j = 0; j < HID; j++) {
        unsigned long long a2 = pack2(h1[j]);
        const ulonglong2* row = (const ulonglong2*)&sW2[j * 16];
        #pragma unroll
        for (int cc = 0; cc < 8; cc++) {
            ulonglong2 w = row[cc];
            fma2(acc[2 * cc],     a2, w.x);
            fma2(acc[2 * cc + 1], a2, w.y);
        }
    }

    // relu + write my neighbor's 32 channels to shared (row = lane, stride 33)
    float* myrow = &red[wlocal][lane * 33];
    #pragma unroll
    for (int c = 0; c < 16; c++) {
        unsigned int lo, hi;
        asm("mov.b64 {%0, %1}, %2;" : "=r"(lo), "=r"(hi) : "l"(acc[c]));
        myrow[2 * c]     = fmaxf(__uint_as_float(lo), 0.f);
        myrow[2 * c + 1] = fmaxf(__uint_as_float(hi), 0.f);
    }
    __syncwarp();

    // Transpose-reduce: lane = channel, max over 32 neighbors (conflict-free)
    float m = red[wlocal][lane];
    #pragma unroll
    for (int d = 1; d < DEG; d++)
        m = fmaxf(m, red[wlocal][d * 33 + lane]);

    out[warp * BOT + lane] = m;
}

extern "C" void kernel_launch(void* const* d_in, const int* in_sizes, int n_in,
                              void* d_out, int out_size) {
    const float* corr  = (const float*)d_in[0];   // [N, 65, 2]
    const int*   nei   = (const int*)d_in[1];     // [N*32, 3]
    // d_in[2] = lstm_state (unused)
    const float* W_se  = (const float*)d_in[3];   // [2, 32]
    const float* b_se  = (const float*)d_in[4];   // [32]
    const float* W1    = (const float*)d_in[5];   // [32, 16]
    const float* b1    = (const float*)d_in[6];   // [16]
    const float* W2    = (const float*)d_in[7];   // [16, 32]
    const float* b2    = (const float*)d_in[8];   // [32]
    float* out = (float*)d_out;

    setup_weights_kernel<<<1, 32>>>(W_se, b_se, W1, b1);

    int threads = WARPS_PER_BLOCK * 32;
    int blocks  = (N_NODES + WARPS_PER_BLOCK - 1) / WARPS_PER_BLOCK;
    pooling_net_kernel<<<blocks, threads>>>((const float2*)corr, nei, W2, b2, out);
}

// round 2
// speedup vs baseline: 1.8073x; 1.8073x over previous
#include <cuda_runtime.h>
#include <cstdint>

#define N_NODES 50000
#define A_DIM   65
#define DEG     32
#define HID     16
#define BOT     32
#define WARPS_PER_BLOCK 4

// All weights published to the constant bank (separate LDC/LDCU port -> frees L1 crossbar)
struct WPack {
    float4 L1[HID];          // (Wc0[j], Wc1[j], bc[j], 0)  composed 2->16 layer
    float  b2[BOT];          // 32
    float  W2[HID * BOT];    // [16][32] row-major
};
__constant__ WPack cw;
__device__   WPack g_stage;

__global__ void setup_weights_kernel(const float* __restrict__ W_se,
                                     const float* __restrict__ b_se,
                                     const float* __restrict__ W1,
                                     const float* __restrict__ b1,
                                     const float* __restrict__ W2,
                                     const float* __restrict__ b2) {
    int t = threadIdx.x;
    if (t < HID) {
        // Compose: Wc = W_se @ W1 (2x16), bc = b_se @ W1 + b1
        float wc0 = 0.f, wc1 = 0.f, bc = b1[t];
        #pragma unroll
        for (int e = 0; e < 32; e++) {
            float w1ej = W1[e * HID + t];
            wc0 = fmaf(W_se[e],      w1ej, wc0);
            wc1 = fmaf(W_se[32 + e], w1ej, wc1);
            bc  = fmaf(b_se[e],      w1ej, bc);
        }
        g_stage.L1[t] = make_float4(wc0, wc1, bc, 0.f);
    }
    for (int i = t; i < HID * BOT; i += blockDim.x) g_stage.W2[i] = W2[i];
    if (t < BOT) g_stage.b2[t] = b2[t];
}

__device__ __forceinline__ void fma2(unsigned long long& acc,
                                     unsigned long long a,
                                     unsigned long long b) {
    asm("fma.rn.f32x2 %0, %1, %2, %0;" : "+l"(acc) : "l"(a), "l"(b));
}
__device__ __forceinline__ unsigned long long pack2(float v) {
    unsigned long long r;
    asm("mov.b64 %0, {%1, %1};" : "=l"(r) : "r"(__float_as_uint(v)));
    return r;
}

// Each warp processes TWO nodes; lane d = neighbor d of both nodes.
// Every 16B weight fetch from the constant port feeds 4 FFMA2.
__global__ __launch_bounds__(WARPS_PER_BLOCK * 32, 4)
void pooling_net_kernel(const float2* __restrict__ corr,   // [N, 65]
                        const int*    __restrict__ nei,    // [N*32, 3]
                        float*        __restrict__ out) {  // [N, 32]
    // Transpose-reduce scratch: [warp][neighbor][16 u64] with +1 u64 pad (stride 34 floats)
    __shared__ unsigned long long red[WARPS_PER_BLOCK][DEG][17];

    int warp   = (blockIdx.x * blockDim.x + threadIdx.x) >> 5;
    int lane   = threadIdx.x & 31;
    int wl     = (threadIdx.x >> 5);
    int n0     = warp * 2;
    int n1     = n0 + 1;
    if (n0 >= N_NODES) return;

    // Gather both nodes' neighbor coordinates
    int aA = nei[(n0 * DEG + lane) * 3 + 1];
    int aB = nei[(n1 * DEG + lane) * 3 + 1];
    float2 xA = corr[n0 * A_DIM + aA];
    float2 xB = corr[n1 * A_DIM + aB];

    // Layer 1 (composed 2->16) + relu, both nodes
    float h1A[HID], h1B[HID];
    #pragma unroll
    for (int j = 0; j < HID; j++) {
        float4 p = cw.L1[j];                                   // LDC.128, lane-invariant
        h1A[j] = fmaxf(fmaf(xA.x, p.x, fmaf(xA.y, p.y, p.z)), 0.f);
        h1B[j] = fmaxf(fmaf(xB.x, p.x, fmaf(xB.y, p.y, p.z)), 0.f);
    }

    // Layer 2 (16->32) packed f32x2, weights shared across the two nodes
    unsigned long long accA[16], accB[16];
    const unsigned long long* b2v = (const unsigned long long*)cw.b2;
    #pragma unroll
    for (int c = 0; c < 16; c++) { accA[c] = b2v[c]; accB[c] = b2v[c]; }

    const ulonglong2* w2v = (const ulonglong2*)cw.W2;          // 8 x 16B per row
    #pragma unroll
    for (int j = 0; j < HID; j++) {
        unsigned long long mA = pack2(h1A[j]);
        unsigned long long mB = pack2(h1B[j]);
        #pragma unroll
        for (int cc = 0; cc < 8; cc++) {
            ulonglong2 w = w2v[j * 8 + cc];                    // LDC.128, lane-invariant
            fma2(accA[2 * cc],     mA, w.x);
            fma2(accA[2 * cc + 1], mA, w.y);
            fma2(accB[2 * cc],     mB, w.x);
            fma2(accB[2 * cc + 1], mB, w.y);
        }
    }

    // Epilogue node 0: transpose via shared, then per-channel max.
    // relu is folded into the pool: max_d relu(x) = max(0, max_d x).
    {
        unsigned long long* myrow = &red[wl][lane][0];
        #pragma unroll
        for (int c = 0; c < 16; c++) myrow[c] = accA[c];       // STS.64, conflict-free
        __syncwarp();
        const float* rf = (const float*)&red[wl][0][0];
        float m = 0.f;
        #pragma unroll
        for (int d = 0; d < DEG; d++) m = fmaxf(m, rf[d * 34 + lane]);
        out[n0 * BOT + lane] = m;
        __syncwarp();
    }
    // Epilogue node 1 (reuse scratch)
    {
        unsigned long long* myrow = &red[wl][lane][0];
        #pragma unroll
        for (int c = 0; c < 16; c++) myrow[c] = accB[c];
        __syncwarp();
        const float* rf = (const float*)&red[wl][0][0];
        float m = 0.f;
        #pragma unroll
        for (int d = 0; d < DEG; d++) m = fmaxf(m, rf[d * 34 + lane]);
        out[n1 * BOT + lane] = m;
    }
}

extern "C" void kernel_launch(void* const* d_in, const int* in_sizes, int n_in,
                              void* d_out, int out_size) {
    const float* corr  = (const float*)d_in[0];   // [N, 65, 2]
    const int*   nei   = (const int*)d_in[1];     // [N*32, 3]
    // d_in[2] = lstm_state (dead)
    const float* W_se  = (const float*)d_in[3];
    const float* b_se  = (const float*)d_in[4];
    const float* W1    = (const float*)d_in[5];
    const float* b1    = (const float*)d_in[6];
    const float* W2    = (const float*)d_in[7];
    const float* b2    = (const float*)d_in[8];
    float* out = (float*)d_out;

    setup_weights_kernel<<<1, 128>>>(W_se, b_se, W1, b1, W2, b2);

    void* stage_ptr = nullptr;
    cudaGetSymbolAddress(&stage_ptr, g_stage);
    cudaMemcpyToSymbolAsync(cw, stage_ptr, sizeof(WPack), 0,
                            cudaMemcpyDeviceToDevice, 0);

    int warps  = (N_NODES + 1) / 2;                       // 2 nodes per warp
    int blocks = (warps + WARPS_PER_BLOCK - 1) / WARPS_PER_BLOCK;
    pooling_net_kernel<<<blocks, WARPS_PER_BLOCK * 32>>>((const float2*)corr, nei, out);
}